// round 5
// baseline (speedup 1.0000x reference)
#include <cuda_runtime.h>
#include <cuda_fp16.h>
#include <cstdint>

#define HIDDEN 1024
#define NHEADS 16
#define HDIM 64
#define BATCH 2
#define SEQ 2048
#define MTOT (BATCH*SEQ)

typedef unsigned long long ull;

// ---- packed fp32x2 helpers (attention) ------------------------------------
__device__ __forceinline__ ull dup2(float x) {
    ull r; asm("mov.b64 %0, {%1, %1};" : "=l"(r) : "f"(x)); return r;
}
__device__ __forceinline__ ull pack2(float lo, float hi) {
    ull r; asm("mov.b64 %0, {%1, %2};" : "=l"(r) : "f"(lo), "f"(hi)); return r;
}
__device__ __forceinline__ void unpack2(ull v, float& lo, float& hi) {
    asm("mov.b64 {%0, %1}, %2;" : "=f"(lo), "=f"(hi) : "l"(v));
}
__device__ __forceinline__ void fma2(ull& d, ull a, ull b) {
    asm("fma.rn.f32x2 %0, %1, %2, %0;" : "+l"(d) : "l"(a), "l"(b));
}
__device__ __forceinline__ ull mul2(ull a, ull b) {
    ull d; asm("mul.rn.f32x2 %0, %1, %2;" : "=l"(d) : "l"(a), "l"(b)); return d;
}

// context scratch, [b, s, h*64+d]
__device__ float g_ctx[(size_t)MTOT * HIDDEN];

// ======================= mma.sync (HMMA) helpers ============================
__device__ __forceinline__ uint32_t smem_u32(const void* p) {
    uint32_t a;
    asm("{ .reg .u64 t; cvta.to.shared.u64 t, %1; cvt.u32.u64 %0, t; }"
        : "=r"(a) : "l"(p));
    return a;
}
__device__ __forceinline__ void ldm4(uint32_t& r0, uint32_t& r1,
                                     uint32_t& r2, uint32_t& r3, uint32_t a) {
    asm volatile("ldmatrix.sync.aligned.m8n8.x4.shared.b16 {%0,%1,%2,%3}, [%4];"
                 : "=r"(r0), "=r"(r1), "=r"(r2), "=r"(r3) : "r"(a));
}
__device__ __forceinline__ void mma_f16(float d[4], const uint32_t a[4],
                                        const uint32_t b[2]) {
    asm volatile(
        "mma.sync.aligned.m16n8k16.row.col.f32.f16.f16.f32 "
        "{%0,%1,%2,%3}, {%4,%5,%6,%7}, {%8,%9}, {%0,%1,%2,%3};"
        : "+f"(d[0]), "+f"(d[1]), "+f"(d[2]), "+f"(d[3])
        : "r"(a[0]), "r"(a[1]), "r"(a[2]), "r"(a[3]), "r"(b[0]), "r"(b[1]));
}
__device__ __forceinline__ uint32_t f22h(float x, float y) {
    __half2 h = __floats2half2_rn(x, y);
    return *(uint32_t*)&h;
}

#define ASTR 40   // halves per smem row (32 data + 8 pad) -> conflict-free ldmatrix

// ---------------------------------------------------------------------------
// fp16x3 HMMA GEMM mainloop: 128x128 tile, K=1024, k-chunks of 32.
// 8 warps, each 32m x 64n. acc[2][8][4] fp32.
// ---------------------------------------------------------------------------
__device__ __forceinline__ void hmma_gemm_main(
    const float* __restrict__ Ag, const float* __restrict__ W, int N,
    int bm, int bn, int tid,
    __half (*sm)[5120],        // [4][128*40]: Ah, Al, Bh, Bl
    float acc[2][8][4])
{
    const int lane = tid & 31, wid = tid >> 5;
    const int m_off = (wid & 3) * 32, n_off = (wid >> 2) * 64;
    __half* Ah = sm[0]; __half* Al = sm[1];
    __half* Bh = sm[2]; __half* Bl = sm[3];
    const uint32_t uAh = smem_u32(Ah), uAl = smem_u32(Al);
    const uint32_t uBh = smem_u32(Bh), uBl = smem_u32(Bl);

    // fragment-load address offsets (constant across chunks)
    const int arow = lane & 15;
    const int acolb = (lane >> 4) << 3;
    const int brow = (lane & 7) + ((lane >> 4) << 3);
    const int bcolb = ((lane >> 3) & 1) << 3;

    for (int c = 0; c < 32; c++) {
        int k0 = c * 32;
        __syncthreads();
        // stage A [128 x 32] h/l
        for (int i = tid; i < 1024; i += 256) {
            int row = i >> 3, q = i & 7;
            float4 v = *(const float4*)(Ag + (size_t)(bm + row) * HIDDEN + k0 + q * 4);
            float hx = __half2float(__float2half_rn(v.x));
            float hy = __half2float(__float2half_rn(v.y));
            float hz = __half2float(__float2half_rn(v.z));
            float hw = __half2float(__float2half_rn(v.w));
            int off = row * ASTR + q * 4;
            *(uint32_t*)&Ah[off]     = f22h(hx, hy);
            *(uint32_t*)&Ah[off + 2] = f22h(hz, hw);
            *(uint32_t*)&Al[off]     = f22h(v.x - hx, v.y - hy);
            *(uint32_t*)&Al[off + 2] = f22h(v.z - hz, v.w - hw);
        }
        // stage B: W[k][n] -> smem [n][k] h/l
        for (int i = tid; i < 1024; i += 256) {
            int n = i & 127, kq = i >> 7;
            const float* wp = W + (size_t)(k0 + kq * 4) * N + bn + n;
            float e0 = wp[0], e1 = wp[N], e2 = wp[2 * N], e3 = wp[3 * N];
            float h0 = __half2float(__float2half_rn(e0));
            float h1 = __half2float(__float2half_rn(e1));
            float h2 = __half2float(__float2half_rn(e2));
            float h3 = __half2float(__float2half_rn(e3));
            int off = n * ASTR + kq * 4;
            *(uint32_t*)&Bh[off]     = f22h(h0, h1);
            *(uint32_t*)&Bh[off + 2] = f22h(h2, h3);
            *(uint32_t*)&Bl[off]     = f22h(e0 - h0, e1 - h1);
            *(uint32_t*)&Bl[off + 2] = f22h(e2 - h2, e3 - h3);
        }
        __syncthreads();

#pragma unroll
        for (int kk = 0; kk < 32; kk += 16) {
            uint32_t aH[2][4], aL[2][4], bH[8][2], bL[8][2];
#pragma unroll
            for (int t = 0; t < 2; t++) {
                uint32_t off = (uint32_t)(((m_off + t * 16 + arow) * ASTR
                                           + kk + acolb) * 2);
                ldm4(aH[t][0], aH[t][1], aH[t][2], aH[t][3], uAh + off);
                ldm4(aL[t][0], aL[t][1], aL[t][2], aL[t][3], uAl + off);
            }
#pragma unroll
            for (int p = 0; p < 4; p++) {
                uint32_t off = (uint32_t)(((n_off + p * 16 + brow) * ASTR
                                           + kk + bcolb) * 2);
                ldm4(bH[2 * p][0], bH[2 * p][1], bH[2 * p + 1][0], bH[2 * p + 1][1],
                     uBh + off);
                ldm4(bL[2 * p][0], bL[2 * p][1], bL[2 * p + 1][0], bL[2 * p + 1][1],
                     uBl + off);
            }
#pragma unroll
            for (int mt = 0; mt < 2; mt++)
#pragma unroll
                for (int nt = 0; nt < 8; nt++) {
                    mma_f16(acc[mt][nt], aH[mt], bH[nt]);
                    mma_f16(acc[mt][nt], aH[mt], bL[nt]);
                    mma_f16(acc[mt][nt], aL[mt], bH[nt]);
                }
        }
    }
}

// ---------------------------------------------------------------------------
// GEMM 1 (HMMA): qkv = x @ W_qkv + b_qkv -> scatter q/k/v [B,h,S,d]
// ---------------------------------------------------------------------------
__global__ __launch_bounds__(256, 1) void gemm_qkv_mma(
    const float* __restrict__ A, const float* __restrict__ W,
    const float* __restrict__ bias,
    float* __restrict__ qo, float* __restrict__ ko, float* __restrict__ vo)
{
    __shared__ __half sm[4][5120];
    int tid = threadIdx.x, lane = tid & 31, wid = tid >> 5;
    int bm = blockIdx.y * 128, bn = blockIdx.x * 128;
    float acc[2][8][4] = {};

    hmma_gemm_main(A, W, 3 * HIDDEN, bm, bn, tid, sm, acc);

    const int m_off = (wid & 3) * 32, n_off = (wid >> 2) * 64;
    int r = lane >> 2, c2 = (lane & 3) << 1;
#pragma unroll
    for (int mt = 0; mt < 2; mt++) {
        int m0 = bm + m_off + mt * 16 + r;
        int m1 = m0 + 8;
        int bb0 = m0 >> 11, s0 = m0 & (SEQ - 1);
        int bb1 = m1 >> 11, s1 = m1 & (SEQ - 1);
#pragma unroll
        for (int nt = 0; nt < 8; nt++) {
            int n = bn + n_off + nt * 8 + c2;
            float2 bv = *(const float2*)&bias[n];
            int t = n >> 10, hh = (n >> 6) & 15, dc = n & 63;
            float* base = (t == 0) ? qo : ((t == 1) ? ko : vo);
            float2 w0 = make_float2(acc[mt][nt][0] + bv.x, acc[mt][nt][1] + bv.y);
            float2 w1 = make_float2(acc[mt][nt][2] + bv.x, acc[mt][nt][3] + bv.y);
            *(float2*)&base[((size_t)(bb0 * NHEADS + hh) * SEQ + s0) * HDIM + dc] = w0;
            *(float2*)&base[((size_t)(bb1 * NHEADS + hh) * SEQ + s1) * HDIM + dc] = w1;
        }
    }
}

// ---------------------------------------------------------------------------
// GEMM 2 (HMMA): output = ctx @ W_out + b_out
// ---------------------------------------------------------------------------
__global__ __launch_bounds__(256, 1) void gemm_out_mma(
    const float* __restrict__ W, const float* __restrict__ bias,
    float* __restrict__ C)
{
    __shared__ __half sm[4][5120];
    int tid = threadIdx.x, lane = tid & 31, wid = tid >> 5;
    int bm = blockIdx.y * 128, bn = blockIdx.x * 128;
    float acc[2][8][4] = {};

    hmma_gemm_main(g_ctx, W, HIDDEN, bm, bn, tid, sm, acc);

    const int m_off = (wid & 3) * 32, n_off = (wid >> 2) * 64;
    int r = lane >> 2, c2 = (lane & 3) << 1;
#pragma unroll
    for (int mt = 0; mt < 2; mt++) {
        int m0 = bm + m_off + mt * 16 + r;
        int m1 = m0 + 8;
#pragma unroll
        for (int nt = 0; nt < 8; nt++) {
            int n = bn + n_off + nt * 8 + c2;
            float2 bv = *(const float2*)&bias[n];
            float2 w0 = make_float2(acc[mt][nt][0] + bv.x, acc[mt][nt][1] + bv.y);
            float2 w1 = make_float2(acc[mt][nt][2] + bv.x, acc[mt][nt][3] + bv.y);
            *(float2*)&C[(size_t)m0 * HIDDEN + n] = w0;
            *(float2*)&C[(size_t)m1 * HIDDEN + n] = w1;
        }
    }
}

// ---------------------------------------------------------------------------
// Flash attention (unchanged): FFMA2, conflict-free key map.
// ---------------------------------------------------------------------------
#define APAD 68
#define ATTN_SMEM_FLOATS (3 * 64 * APAD + 64)

__global__ __launch_bounds__(256) void attn_kernel(
    const float* __restrict__ Q, const float* __restrict__ Kg,
    const float* __restrict__ Vg, const int* __restrict__ mask)
{
    extern __shared__ float sm[];
    float* QsT = sm;                  // [d=64][row=64] stride APAD
    float* Ks  = QsT + 64 * APAD;     // [key=64][d=64] ; aliased as PsT
    float* Vs  = Ks + 64 * APAD;      // [t=64][d=64]
    float* mbias = Vs + 64 * APAD;    // 64

    int tid = threadIdx.x;
    int qt = blockIdx.x, h = blockIdx.y, b = blockIdx.z;
    int bh = b * NHEADS + h;
    int qbase = qt * 64;
    const float* Qp = Q + ((size_t)bh * SEQ + qbase) * HDIM;
    const float* Kp = Kg + (size_t)bh * SEQ * HDIM;
    const float* Vp = Vg + (size_t)bh * SEQ * HDIM;

    for (int i = tid; i < 1024; i += 256) {
        float4 v = ((const float4*)Qp)[i];
        int r = i >> 4, c = (i & 15) << 2;
        QsT[(c + 0) * APAD + r] = v.x;
        QsT[(c + 1) * APAD + r] = v.y;
        QsT[(c + 2) * APAD + r] = v.z;
        QsT[(c + 3) * APAD + r] = v.w;
    }

    const int tx = tid & 15, ty = tid >> 4;
    ull o2[2][4] = {};
    float mrow[4] = {-1e30f, -1e30f, -1e30f, -1e30f};
    float lrow[4] = {};
    const float scale = 0.125f;

    for (int kt = 0; kt <= qt; kt++) {
        __syncthreads();
        {
            const float4* kg4 = (const float4*)(Kp + (size_t)(kt * 64) * HDIM);
            const float4* vg4 = (const float4*)(Vp + (size_t)(kt * 64) * HDIM);
            for (int i = tid; i < 1024; i += 256) {
                int r = i >> 4, c = (i & 15) << 2;
                *(float4*)&Ks[r * APAD + c] = kg4[i];
                *(float4*)&Vs[r * APAD + c] = vg4[i];
            }
            if (tid < 64)
                mbias[tid] = (mask[b * SEQ + kt * 64 + tid] == 0) ? -1e30f : 0.0f;
        }
        __syncthreads();

        ull sv2[2][4] = {};
        for (int d0 = 0; d0 < 64; d0 += 4) {
            float kf[4][4];
#pragma unroll
            for (int j = 0; j < 4; j++)
                *(float4*)kf[j] = *(const float4*)&Ks[(tx + 16 * j) * APAD + d0];
#pragma unroll
            for (int dd = 0; dd < 4; dd++) {
                ulonglong2 q2 = *(const ulonglong2*)&QsT[(d0 + dd) * APAD + (ty << 2)];
#pragma unroll
                for (int j = 0; j < 4; j++) {
                    ull kd = dup2(kf[j][dd]);
                    fma2(sv2[0][j], q2.x, kd);
                    fma2(sv2[1][j], q2.y, kd);
                }
            }
        }
        float s[4][4];
#pragma unroll
        for (int ip = 0; ip < 2; ip++)
#pragma unroll
            for (int j = 0; j < 4; j++)
                unpack2(sv2[ip][j], s[2 * ip][j], s[2 * ip + 1][j]);

        float mb[4];
#pragma unroll
        for (int j = 0; j < 4; j++) mb[j] = mbias[tx + 16 * j];
        bool diag = (kt == qt);
#pragma unroll
        for (int i = 0; i < 4; i++) {
            int qpos = (ty << 2) + i;
#pragma unroll
            for (int j = 0; j < 4; j++) {
                int kpos = tx + 16 * j;
                float v = s[i][j] * scale + mb[j];
                if (diag && kpos > qpos) v = -1e30f;
                s[i][j] = v;
            }
        }

        float fac[4];
#pragma unroll
        for (int i = 0; i < 4; i++) {
            float mx = fmaxf(fmaxf(s[i][0], s[i][1]), fmaxf(s[i][2], s[i][3]));
#pragma unroll
            for (int off = 8; off >= 1; off >>= 1)
                mx = fmaxf(mx, __shfl_xor_sync(0xffffffffu, mx, off, 16));
            float mnew = fmaxf(mrow[i], mx);
            fac[i] = __expf(mrow[i] - mnew);
            mrow[i] = mnew;
            float rs = 0.f;
#pragma unroll
            for (int j = 0; j < 4; j++) {
                float p = __expf(s[i][j] - mnew);
                s[i][j] = p;
                rs += p;
            }
#pragma unroll
            for (int off = 8; off >= 1; off >>= 1)
                rs += __shfl_xor_sync(0xffffffffu, rs, off, 16);
            lrow[i] = lrow[i] * fac[i] + rs;
        }
        ull facp0 = pack2(fac[0], fac[1]);
        ull facp1 = pack2(fac[2], fac[3]);
#pragma unroll
        for (int j = 0; j < 4; j++) {
            o2[0][j] = mul2(o2[0][j], facp0);
            o2[1][j] = mul2(o2[1][j], facp1);
        }

        __syncthreads();
        float* PsT = Ks;
#pragma unroll
        for (int j = 0; j < 4; j++)
#pragma unroll
            for (int i = 0; i < 4; i++)
                PsT[(tx + 16 * j) * APAD + (ty << 2) + i] = s[i][j];
        __syncthreads();

#pragma unroll 4
        for (int t = 0; t < 64; t++) {
            ulonglong2 p2 = *(const ulonglong2*)&PsT[t * APAD + (ty << 2)];
            float4 v4 = *(const float4*)&Vs[t * APAD + (tx << 2)];
            ull vd;
            vd = dup2(v4.x); fma2(o2[0][0], p2.x, vd); fma2(o2[1][0], p2.y, vd);
            vd = dup2(v4.y); fma2(o2[0][1], p2.x, vd); fma2(o2[1][1], p2.y, vd);
            vd = dup2(v4.z); fma2(o2[0][2], p2.x, vd); fma2(o2[1][2], p2.y, vd);
            vd = dup2(v4.w); fma2(o2[0][3], p2.x, vd); fma2(o2[1][3], p2.y, vd);
        }
    }

    float of[4][4];
#pragma unroll
    for (int ip = 0; ip < 2; ip++)
#pragma unroll
        for (int j = 0; j < 4; j++)
            unpack2(o2[ip][j], of[2 * ip][j], of[2 * ip + 1][j]);
#pragma unroll
    for (int i = 0; i < 4; i++) {
        float inv = 1.0f / lrow[i];
        int srow = qbase + (ty << 2) + i;
        float4 w = make_float4(of[i][0] * inv, of[i][1] * inv,
                               of[i][2] * inv, of[i][3] * inv);
        *(float4*)&g_ctx[(size_t)(b * SEQ + srow) * HIDDEN + h * HDIM + (tx << 2)] = w;
    }
}

// ---------------------------------------------------------------------------
extern "C" void kernel_launch(void* const* d_in, const int* in_sizes, int n_in,
                              void* d_out, int out_size) {
    const float* x    = (const float*)d_in[0];
    const int*   mask = (const int*)d_in[1];
    const float* Wqkv = (const float*)d_in[2];
    const float* bqkv = (const float*)d_in[3];
    const float* Wout = (const float*)d_in[4];
    const float* bout = (const float*)d_in[5];

    float* out = (float*)d_out;                     // [B,S,H]
    float* qo = out + (size_t)MTOT * HIDDEN;        // [B,h,S,d]
    float* ko = qo + (size_t)MTOT * HIDDEN;
    float* vo = ko + (size_t)MTOT * HIDDEN;

    const int attn_smem = ATTN_SMEM_FLOATS * (int)sizeof(float);
    cudaFuncSetAttribute(attn_kernel,
                         cudaFuncAttributeMaxDynamicSharedMemorySize, attn_smem);

    gemm_qkv_mma<<<dim3(24, 32), 256>>>(x, Wqkv, bqkv, qo, ko, vo);
    attn_kernel<<<dim3(SEQ / 64, NHEADS, BATCH), 256, attn_smem>>>(qo, ko, vo, mask);
    gemm_out_mma<<<dim3(8, 32), 256>>>(Wout, bout, out);
}

// round 6
// speedup vs baseline: 1.5225x; 1.5225x over previous
#include <cuda_runtime.h>
#include <cuda_fp16.h>
#include <cstdint>

#define HIDDEN 1024
#define NHEADS 16
#define HDIM 64
#define BATCH 2
#define SEQ 2048
#define MTOT (BATCH*SEQ)

typedef unsigned long long ull;

// ---- packed fp32x2 helpers (attention) ------------------------------------
__device__ __forceinline__ ull dup2(float x) {
    ull r; asm("mov.b64 %0, {%1, %1};" : "=l"(r) : "f"(x)); return r;
}
__device__ __forceinline__ ull pack2(float lo, float hi) {
    ull r; asm("mov.b64 %0, {%1, %2};" : "=l"(r) : "f"(lo), "f"(hi)); return r;
}
__device__ __forceinline__ void unpack2(ull v, float& lo, float& hi) {
    asm("mov.b64 {%0, %1}, %2;" : "=f"(lo), "=f"(hi) : "l"(v));
}
__device__ __forceinline__ void fma2(ull& d, ull a, ull b) {
    asm("fma.rn.f32x2 %0, %1, %2, %0;" : "+l"(d) : "l"(a), "l"(b));
}
__device__ __forceinline__ ull mul2(ull a, ull b) {
    ull d; asm("mul.rn.f32x2 %0, %1, %2;" : "=l"(d) : "l"(a), "l"(b)); return d;
}

// ---- fp16 h/l scratch (preconverted operands) ------------------------------
__device__ __half g_xh[(size_t)MTOT * HIDDEN];
__device__ __half g_xl[(size_t)MTOT * HIDDEN];
__device__ __half g_wqkvT_h[(size_t)3 * HIDDEN * HIDDEN];
__device__ __half g_wqkvT_l[(size_t)3 * HIDDEN * HIDDEN];
__device__ __half g_woutT_h[(size_t)HIDDEN * HIDDEN];
__device__ __half g_woutT_l[(size_t)HIDDEN * HIDDEN];
__device__ __half g_ctxh[(size_t)MTOT * HIDDEN];
__device__ __half g_ctxl[(size_t)MTOT * HIDDEN];

// ======================= misc helpers =======================================
__device__ __forceinline__ uint32_t smem_u32(const void* p) {
    uint32_t a;
    asm("{ .reg .u64 t; cvta.to.shared.u64 t, %1; cvt.u32.u64 %0, t; }"
        : "=r"(a) : "l"(p));
    return a;
}
__device__ __forceinline__ void ldm4(uint32_t& r0, uint32_t& r1,
                                     uint32_t& r2, uint32_t& r3, uint32_t a) {
    asm volatile("ldmatrix.sync.aligned.m8n8.x4.shared.b16 {%0,%1,%2,%3}, [%4];"
                 : "=r"(r0), "=r"(r1), "=r"(r2), "=r"(r3) : "r"(a));
}
__device__ __forceinline__ void mma_f16(float d[4], const uint32_t a[4],
                                        const uint32_t b[2]) {
    asm volatile(
        "mma.sync.aligned.m16n8k16.row.col.f32.f16.f16.f32 "
        "{%0,%1,%2,%3}, {%4,%5,%6,%7}, {%8,%9}, {%0,%1,%2,%3};"
        : "+f"(d[0]), "+f"(d[1]), "+f"(d[2]), "+f"(d[3])
        : "r"(a[0]), "r"(a[1]), "r"(a[2]), "r"(a[3]), "r"(b[0]), "r"(b[1]));
}
__device__ __forceinline__ void cpa16(uint32_t dst, const void* src) {
    asm volatile("cp.async.cg.shared.global [%0], [%1], 16;"
                 :: "r"(dst), "l"(src) : "memory");
}
#define CP_COMMIT() asm volatile("cp.async.commit_group;" ::: "memory")
#define CP_WAIT1()  asm volatile("cp.async.wait_group 1;" ::: "memory")
#define CP_WAIT0()  asm volatile("cp.async.wait_group 0;" ::: "memory")

#define ASTR 40     // halves per smem row (32 data + 8 pad)
#define BUFH (128 * ASTR)           // halves per operand array
#define GEMM_SMEM_BYTES (2 * 4 * BUFH * 2)   // 2 bufs x 4 arrays x halves

// ---------------------------------------------------------------------------
// Conversion kernels
// ---------------------------------------------------------------------------
__global__ __launch_bounds__(256) void conv_split_kernel(
    const float* __restrict__ src, __half* __restrict__ dh,
    __half* __restrict__ dl, int n4)
{
    int i = blockIdx.x * 256 + threadIdx.x;
    if (i >= n4) return;
    float4 v = ((const float4*)src)[i];
    __half2 h0 = __floats2half2_rn(v.x, v.y);
    __half2 h1 = __floats2half2_rn(v.z, v.w);
    float2 f0 = __half22float2(h0), f1 = __half22float2(h1);
    __half2 l0 = __floats2half2_rn(v.x - f0.x, v.y - f0.y);
    __half2 l1 = __floats2half2_rn(v.z - f1.x, v.w - f1.y);
    ((uint2*)dh)[i] = make_uint2(*(uint32_t*)&h0, *(uint32_t*)&h1);
    ((uint2*)dl)[i] = make_uint2(*(uint32_t*)&l0, *(uint32_t*)&l1);
}

// W[k][n] fp32 -> WT[n][k] fp16 h/l (K = HIDDEN fixed)
__global__ __launch_bounds__(256) void conv_wT_kernel(
    const float* __restrict__ W, __half* __restrict__ WhT,
    __half* __restrict__ WlT, int N)
{
    __shared__ float ts[32][33];
    int n0 = blockIdx.x * 32, k0 = blockIdx.y * 32;
    int tx = threadIdx.x & 31, ty = threadIdx.x >> 5;   // 32 x 8
#pragma unroll
    for (int r = 0; r < 32; r += 8)
        ts[ty + r][tx] = W[(size_t)(k0 + ty + r) * N + n0 + tx];
    __syncthreads();
#pragma unroll
    for (int r = 0; r < 32; r += 8) {
        float v = ts[tx][ty + r];
        __half h = __float2half_rn(v);
        __half l = __float2half_rn(v - __half2float(h));
        size_t o = (size_t)(n0 + ty + r) * HIDDEN + k0 + tx;
        WhT[o] = h;
        WlT[o] = l;
    }
}

// ---------------------------------------------------------------------------
// HMMA GEMM mainloop: preconverted fp16 h/l, cp.async double-buffered.
// Block 128x128, K=1024 in 32 chunks of 32. 8 warps, 32m x 64n each.
// ---------------------------------------------------------------------------
__device__ __forceinline__ void stage_chunk(
    const __half* __restrict__ Ah, const __half* __restrict__ Al,
    const __half* __restrict__ BhT, const __half* __restrict__ BlT,
    int bm, int bn, int k0, int tid, uint32_t sbuf)
{
    // layout within buffer: [Ah | Al | Bh | Bl], each 128*ASTR halves
    for (int i = tid; i < 512; i += 256) {
        int row = i >> 2, q = i & 3;
        uint32_t doff = (uint32_t)((row * ASTR + q * 8) * 2);
        size_t soA = (size_t)(bm + row) * HIDDEN + k0 + q * 8;
        size_t soB = (size_t)(bn + row) * HIDDEN + k0 + q * 8;
        cpa16(sbuf + doff,                    Ah + soA);
        cpa16(sbuf + BUFH * 2 + doff,         Al + soA);
        cpa16(sbuf + 2 * BUFH * 2 + doff,     BhT + soB);
        cpa16(sbuf + 3 * BUFH * 2 + doff,     BlT + soB);
    }
}

__device__ __forceinline__ void hmma_gemm_main(
    const __half* __restrict__ Ah, const __half* __restrict__ Al,
    const __half* __restrict__ BhT, const __half* __restrict__ BlT,
    int bm, int bn, int tid, uint32_t sbase, float acc[2][8][4])
{
    const int lane = tid & 31, wid = tid >> 5;
    const int m_off = (wid & 3) * 32, n_off = (wid >> 2) * 64;
    const int arow = lane & 15;
    const int acolb = (lane >> 4) << 3;
    const int brow = (lane & 7) + ((lane >> 4) << 3);
    const int bcolb = ((lane >> 3) & 1) << 3;
    const uint32_t bufbytes = 4 * BUFH * 2;

    stage_chunk(Ah, Al, BhT, BlT, bm, bn, 0, tid, sbase);
    CP_COMMIT();

    for (int c = 0; c < 32; c++) {
        uint32_t cur = sbase + (uint32_t)(c & 1) * bufbytes;
        if (c + 1 < 32) {
            stage_chunk(Ah, Al, BhT, BlT, bm, bn, (c + 1) * 32, tid,
                        sbase + (uint32_t)((c + 1) & 1) * bufbytes);
            CP_COMMIT();
            CP_WAIT1();
        } else {
            CP_WAIT0();
        }
        __syncthreads();

        uint32_t uAh = cur, uAl = cur + BUFH * 2;
        uint32_t uBh = cur + 2 * BUFH * 2, uBl = cur + 3 * BUFH * 2;
#pragma unroll
        for (int kk = 0; kk < 32; kk += 16) {
            uint32_t aH[2][4], aL[2][4], bH[8][2], bL[8][2];
#pragma unroll
            for (int t = 0; t < 2; t++) {
                uint32_t off = (uint32_t)(((m_off + t * 16 + arow) * ASTR
                                           + kk + acolb) * 2);
                ldm4(aH[t][0], aH[t][1], aH[t][2], aH[t][3], uAh + off);
                ldm4(aL[t][0], aL[t][1], aL[t][2], aL[t][3], uAl + off);
            }
#pragma unroll
            for (int p = 0; p < 4; p++) {
                uint32_t off = (uint32_t)(((n_off + p * 16 + brow) * ASTR
                                           + kk + bcolb) * 2);
                ldm4(bH[2 * p][0], bH[2 * p][1], bH[2 * p + 1][0], bH[2 * p + 1][1],
                     uBh + off);
                ldm4(bL[2 * p][0], bL[2 * p][1], bL[2 * p + 1][0], bL[2 * p + 1][1],
                     uBl + off);
            }
#pragma unroll
            for (int mt = 0; mt < 2; mt++)
#pragma unroll
                for (int nt = 0; nt < 8; nt++) {
                    mma_f16(acc[mt][nt], aH[mt], bH[nt]);
                    mma_f16(acc[mt][nt], aH[mt], bL[nt]);
                    mma_f16(acc[mt][nt], aL[mt], bH[nt]);
                }
        }
        __syncthreads();
    }
}

// ---------------------------------------------------------------------------
// GEMM 1 (HMMA): qkv -> scatter q/k/v [B,h,S,d]
// ---------------------------------------------------------------------------
__global__ __launch_bounds__(256, 1) void gemm_qkv_mma(
    const float* __restrict__ bias,
    float* __restrict__ qo, float* __restrict__ ko, float* __restrict__ vo)
{
    extern __shared__ __half dynsm[];
    int tid = threadIdx.x, lane = tid & 31, wid = tid >> 5;
    int bm = blockIdx.y * 128, bn = blockIdx.x * 128;
    float acc[2][8][4] = {};

    hmma_gemm_main(g_xh, g_xl, g_wqkvT_h, g_wqkvT_l, bm, bn, tid,
                   smem_u32(dynsm), acc);

    const int m_off = (wid & 3) * 32, n_off = (wid >> 2) * 64;
    int r = lane >> 2, c2 = (lane & 3) << 1;
#pragma unroll
    for (int mt = 0; mt < 2; mt++) {
        int m0 = bm + m_off + mt * 16 + r;
        int m1 = m0 + 8;
        int bb0 = m0 >> 11, s0 = m0 & (SEQ - 1);
        int bb1 = m1 >> 11, s1 = m1 & (SEQ - 1);
#pragma unroll
        for (int nt = 0; nt < 8; nt++) {
            int n = bn + n_off + nt * 8 + c2;
            float2 bv = *(const float2*)&bias[n];
            int t = n >> 10, hh = (n >> 6) & 15, dc = n & 63;
            float* base = (t == 0) ? qo : ((t == 1) ? ko : vo);
            float2 w0 = make_float2(acc[mt][nt][0] + bv.x, acc[mt][nt][1] + bv.y);
            float2 w1 = make_float2(acc[mt][nt][2] + bv.x, acc[mt][nt][3] + bv.y);
            *(float2*)&base[((size_t)(bb0 * NHEADS + hh) * SEQ + s0) * HDIM + dc] = w0;
            *(float2*)&base[((size_t)(bb1 * NHEADS + hh) * SEQ + s1) * HDIM + dc] = w1;
        }
    }
}

// ---------------------------------------------------------------------------
// GEMM 2 (HMMA): output = ctx @ W_out + b_out
// ---------------------------------------------------------------------------
__global__ __launch_bounds__(256, 1) void gemm_out_mma(
    const float* __restrict__ bias, float* __restrict__ C)
{
    extern __shared__ __half dynsm[];
    int tid = threadIdx.x, lane = tid & 31, wid = tid >> 5;
    int bm = blockIdx.y * 128, bn = blockIdx.x * 128;
    float acc[2][8][4] = {};

    hmma_gemm_main(g_ctxh, g_ctxl, g_woutT_h, g_woutT_l, bm, bn, tid,
                   smem_u32(dynsm), acc);

    const int m_off = (wid & 3) * 32, n_off = (wid >> 2) * 64;
    int r = lane >> 2, c2 = (lane & 3) << 1;
#pragma unroll
    for (int mt = 0; mt < 2; mt++) {
        int m0 = bm + m_off + mt * 16 + r;
        int m1 = m0 + 8;
#pragma unroll
        for (int nt = 0; nt < 8; nt++) {
            int n = bn + n_off + nt * 8 + c2;
            float2 bv = *(const float2*)&bias[n];
            float2 w0 = make_float2(acc[mt][nt][0] + bv.x, acc[mt][nt][1] + bv.y);
            float2 w1 = make_float2(acc[mt][nt][2] + bv.x, acc[mt][nt][3] + bv.y);
            *(float2*)&C[(size_t)m0 * HIDDEN + n] = w0;
            *(float2*)&C[(size_t)m1 * HIDDEN + n] = w1;
        }
    }
}

// ---------------------------------------------------------------------------
// Flash attention: FFMA2, conflict-free key map; epilogue -> ctx fp16 h/l.
// ---------------------------------------------------------------------------
#define APAD 68
#define ATTN_SMEM_FLOATS (3 * 64 * APAD + 64)

__global__ __launch_bounds__(256) void attn_kernel(
    const float* __restrict__ Q, const float* __restrict__ Kg,
    const float* __restrict__ Vg, const int* __restrict__ mask)
{
    extern __shared__ float sm[];
    float* QsT = sm;
    float* Ks  = QsT + 64 * APAD;
    float* Vs  = Ks + 64 * APAD;
    float* mbias = Vs + 64 * APAD;

    int tid = threadIdx.x;
    int qt = blockIdx.x, h = blockIdx.y, b = blockIdx.z;
    int bh = b * NHEADS + h;
    int qbase = qt * 64;
    const float* Qp = Q + ((size_t)bh * SEQ + qbase) * HDIM;
    const float* Kp = Kg + (size_t)bh * SEQ * HDIM;
    const float* Vp = Vg + (size_t)bh * SEQ * HDIM;

    for (int i = tid; i < 1024; i += 256) {
        float4 v = ((const float4*)Qp)[i];
        int r = i >> 4, c = (i & 15) << 2;
        QsT[(c + 0) * APAD + r] = v.x;
        QsT[(c + 1) * APAD + r] = v.y;
        QsT[(c + 2) * APAD + r] = v.z;
        QsT[(c + 3) * APAD + r] = v.w;
    }

    const int tx = tid & 15, ty = tid >> 4;
    ull o2[2][4] = {};
    float mrow[4] = {-1e30f, -1e30f, -1e30f, -1e30f};
    float lrow[4] = {};
    const float scale = 0.125f;

    for (int kt = 0; kt <= qt; kt++) {
        __syncthreads();
        {
            const float4* kg4 = (const float4*)(Kp + (size_t)(kt * 64) * HDIM);
            const float4* vg4 = (const float4*)(Vp + (size_t)(kt * 64) * HDIM);
            for (int i = tid; i < 1024; i += 256) {
                int r = i >> 4, c = (i & 15) << 2;
                *(float4*)&Ks[r * APAD + c] = kg4[i];
                *(float4*)&Vs[r * APAD + c] = vg4[i];
            }
            if (tid < 64)
                mbias[tid] = (mask[b * SEQ + kt * 64 + tid] == 0) ? -1e30f : 0.0f;
        }
        __syncthreads();

        ull sv2[2][4] = {};
        for (int d0 = 0; d0 < 64; d0 += 4) {
            float kf[4][4];
#pragma unroll
            for (int j = 0; j < 4; j++)
                *(float4*)kf[j] = *(const float4*)&Ks[(tx + 16 * j) * APAD + d0];
#pragma unroll
            for (int dd = 0; dd < 4; dd++) {
                ulonglong2 q2 = *(const ulonglong2*)&QsT[(d0 + dd) * APAD + (ty << 2)];
#pragma unroll
                for (int j = 0; j < 4; j++) {
                    ull kd = dup2(kf[j][dd]);
                    fma2(sv2[0][j], q2.x, kd);
                    fma2(sv2[1][j], q2.y, kd);
                }
            }
        }
        float s[4][4];
#pragma unroll
        for (int ip = 0; ip < 2; ip++)
#pragma unroll
            for (int j = 0; j < 4; j++)
                unpack2(sv2[ip][j], s[2 * ip][j], s[2 * ip + 1][j]);

        float mb[4];
#pragma unroll
        for (int j = 0; j < 4; j++) mb[j] = mbias[tx + 16 * j];
        bool diag = (kt == qt);
#pragma unroll
        for (int i = 0; i < 4; i++) {
            int qpos = (ty << 2) + i;
#pragma unroll
            for (int j = 0; j < 4; j++) {
                int kpos = tx + 16 * j;
                float v = s[i][j] * scale + mb[j];
                if (diag && kpos > qpos) v = -1e30f;
                s[i][j] = v;
            }
        }

        float fac[4];
#pragma unroll
        for (int i = 0; i < 4; i++) {
            float mx = fmaxf(fmaxf(s[i][0], s[i][1]), fmaxf(s[i][2], s[i][3]));
#pragma unroll
            for (int off = 8; off >= 1; off >>= 1)
                mx = fmaxf(mx, __shfl_xor_sync(0xffffffffu, mx, off, 16));
            float mnew = fmaxf(mrow[i], mx);
            fac[i] = __expf(mrow[i] - mnew);
            mrow[i] = mnew;
            float rs = 0.f;
#pragma unroll
            for (int j = 0; j < 4; j++) {
                float p = __expf(s[i][j] - mnew);
                s[i][j] = p;
                rs += p;
            }
#pragma unroll
            for (int off = 8; off >= 1; off >>= 1)
                rs += __shfl_xor_sync(0xffffffffu, rs, off, 16);
            lrow[i] = lrow[i] * fac[i] + rs;
        }
        ull facp0 = pack2(fac[0], fac[1]);
        ull facp1 = pack2(fac[2], fac[3]);
#pragma unroll
        for (int j = 0; j < 4; j++) {
            o2[0][j] = mul2(o2[0][j], facp0);
            o2[1][j] = mul2(o2[1][j], facp1);
        }

        __syncthreads();
        float* PsT = Ks;
#pragma unroll
        for (int j = 0; j < 4; j++)
#pragma unroll
            for (int i = 0; i < 4; i++)
                PsT[(tx + 16 * j) * APAD + (ty << 2) + i] = s[i][j];
        __syncthreads();

#pragma unroll 4
        for (int t = 0; t < 64; t++) {
            ulonglong2 p2 = *(const ulonglong2*)&PsT[t * APAD + (ty << 2)];
            float4 v4 = *(const float4*)&Vs[t * APAD + (tx << 2)];
            ull vd;
            vd = dup2(v4.x); fma2(o2[0][0], p2.x, vd); fma2(o2[1][0], p2.y, vd);
            vd = dup2(v4.y); fma2(o2[0][1], p2.x, vd); fma2(o2[1][1], p2.y, vd);
            vd = dup2(v4.z); fma2(o2[0][2], p2.x, vd); fma2(o2[1][2], p2.y, vd);
            vd = dup2(v4.w); fma2(o2[0][3], p2.x, vd); fma2(o2[1][3], p2.y, vd);
        }
    }

    float of[4][4];
#pragma unroll
    for (int ip = 0; ip < 2; ip++)
#pragma unroll
        for (int j = 0; j < 4; j++)
            unpack2(o2[ip][j], of[2 * ip][j], of[2 * ip + 1][j]);
#pragma unroll
    for (int i = 0; i < 4; i++) {
        float inv = 1.0f / lrow[i];
        int srow = qbase + (ty << 2) + i;
        float4 w = make_float4(of[i][0] * inv, of[i][1] * inv,
                               of[i][2] * inv, of[i][3] * inv);
        size_t base = (size_t)(b * SEQ + srow) * HIDDEN + h * HDIM + (tx << 2);
        __half2 h0 = __floats2half2_rn(w.x, w.y);
        __half2 h1 = __floats2half2_rn(w.z, w.w);
        float2 f0 = __half22float2(h0), f1 = __half22float2(h1);
        __half2 l0 = __floats2half2_rn(w.x - f0.x, w.y - f0.y);
        __half2 l1 = __floats2half2_rn(w.z - f1.x, w.w - f1.y);
        *(uint2*)&g_ctxh[base] = make_uint2(*(uint32_t*)&h0, *(uint32_t*)&h1);
        *(uint2*)&g_ctxl[base] = make_uint2(*(uint32_t*)&l0, *(uint32_t*)&l1);
    }
}

// ---------------------------------------------------------------------------
extern "C" void kernel_launch(void* const* d_in, const int* in_sizes, int n_in,
                              void* d_out, int out_size) {
    const float* x    = (const float*)d_in[0];
    const int*   mask = (const int*)d_in[1];
    const float* Wqkv = (const float*)d_in[2];
    const float* bqkv = (const float*)d_in[3];
    const float* Wout = (const float*)d_in[4];
    const float* bout = (const float*)d_in[5];

    float* out = (float*)d_out;                     // [B,S,H]
    float* qo = out + (size_t)MTOT * HIDDEN;        // [B,h,S,d]
    float* ko = qo + (size_t)MTOT * HIDDEN;
    float* vo = ko + (size_t)MTOT * HIDDEN;

    const int attn_smem = ATTN_SMEM_FLOATS * (int)sizeof(float);
    cudaFuncSetAttribute(attn_kernel,
                         cudaFuncAttributeMaxDynamicSharedMemorySize, attn_smem);
    cudaFuncSetAttribute(gemm_qkv_mma,
                         cudaFuncAttributeMaxDynamicSharedMemorySize, GEMM_SMEM_BYTES);
    cudaFuncSetAttribute(gemm_out_mma,
                         cudaFuncAttributeMaxDynamicSharedMemorySize, GEMM_SMEM_BYTES);

    __half *xh, *xl, *wqh, *wql, *woh, *wol;
    cudaGetSymbolAddress((void**)&xh, g_xh);
    cudaGetSymbolAddress((void**)&xl, g_xl);
    cudaGetSymbolAddress((void**)&wqh, g_wqkvT_h);
    cudaGetSymbolAddress((void**)&wql, g_wqkvT_l);
    cudaGetSymbolAddress((void**)&woh, g_woutT_h);
    cudaGetSymbolAddress((void**)&wol, g_woutT_l);

    // conversions
    conv_split_kernel<<<(MTOT * HIDDEN / 4 + 255) / 256, 256>>>(
        x, xh, xl, MTOT * HIDDEN / 4);
    conv_wT_kernel<<<dim3(3 * HIDDEN / 32, HIDDEN / 32), 256>>>(
        Wqkv, wqh, wql, 3 * HIDDEN);
    conv_wT_kernel<<<dim3(HIDDEN / 32, HIDDEN / 32), 256>>>(
        Wout, woh, wol, HIDDEN);

    gemm_qkv_mma<<<dim3(24, 32), 256, GEMM_SMEM_BYTES>>>(bqkv, qo, ko, vo);
    attn_kernel<<<dim3(SEQ / 64, NHEADS, BATCH), 256, attn_smem>>>(qo, ko, vo, mask);
    gemm_out_mma<<<dim3(8, 32), 256, GEMM_SMEM_BYTES>>>(bout, out);
}

// round 9
// speedup vs baseline: 2.2866x; 1.5019x over previous
#include <cuda_runtime.h>
#include <cuda_fp16.h>
#include <cstdint>

#define HIDDEN 1024
#define NHEADS 16
#define HDIM 64
#define BATCH 2
#define SEQ 2048
#define MTOT (BATCH*SEQ)

typedef unsigned long long ull;

// ---- fp16 h/l scratch ------------------------------------------------------
__device__ __half g_xh[(size_t)MTOT * HIDDEN];
__device__ __half g_xl[(size_t)MTOT * HIDDEN];
__device__ __half g_wqkvT_h[(size_t)3 * HIDDEN * HIDDEN];
__device__ __half g_wqkvT_l[(size_t)3 * HIDDEN * HIDDEN];
__device__ __half g_woutT_h[(size_t)HIDDEN * HIDDEN];
__device__ __half g_woutT_l[(size_t)HIDDEN * HIDDEN];
__device__ __half g_ctxh[(size_t)MTOT * HIDDEN];
__device__ __half g_ctxl[(size_t)MTOT * HIDDEN];
// attention operands, [B,h,S,d]; q pre-scaled by 0.125
__device__ __half g_qh[(size_t)MTOT * HIDDEN];
__device__ __half g_ql[(size_t)MTOT * HIDDEN];
__device__ __half g_kh[(size_t)MTOT * HIDDEN];
__device__ __half g_kl[(size_t)MTOT * HIDDEN];
__device__ __half g_vh[(size_t)MTOT * HIDDEN];
__device__ __half g_vl[(size_t)MTOT * HIDDEN];

// ======================= helpers ============================================
__device__ __forceinline__ uint32_t smem_u32(const void* p) {
    uint32_t a;
    asm("{ .reg .u64 t; cvta.to.shared.u64 t, %1; cvt.u32.u64 %0, t; }"
        : "=r"(a) : "l"(p));
    return a;
}
__device__ __forceinline__ void ldm4(uint32_t& r0, uint32_t& r1,
                                     uint32_t& r2, uint32_t& r3, uint32_t a) {
    asm volatile("ldmatrix.sync.aligned.m8n8.x4.shared.b16 {%0,%1,%2,%3}, [%4];"
                 : "=r"(r0), "=r"(r1), "=r"(r2), "=r"(r3) : "r"(a));
}
__device__ __forceinline__ void ldm4t(uint32_t& r0, uint32_t& r1,
                                      uint32_t& r2, uint32_t& r3, uint32_t a) {
    asm volatile("ldmatrix.sync.aligned.m8n8.x4.trans.shared.b16 {%0,%1,%2,%3}, [%4];"
                 : "=r"(r0), "=r"(r1), "=r"(r2), "=r"(r3) : "r"(a));
}
__device__ __forceinline__ void mma_f16(float d[4], const uint32_t a[4],
                                        const uint32_t b[2]) {
    asm volatile(
        "mma.sync.aligned.m16n8k16.row.col.f32.f16.f16.f32 "
        "{%0,%1,%2,%3}, {%4,%5,%6,%7}, {%8,%9}, {%0,%1,%2,%3};"
        : "+f"(d[0]), "+f"(d[1]), "+f"(d[2]), "+f"(d[3])
        : "r"(a[0]), "r"(a[1]), "r"(a[2]), "r"(a[3]), "r"(b[0]), "r"(b[1]));
}
__device__ __forceinline__ void cpa16(uint32_t dst, const void* src) {
    asm volatile("cp.async.cg.shared.global [%0], [%1], 16;"
                 :: "r"(dst), "l"(src) : "memory");
}
#define CP_COMMIT() asm volatile("cp.async.commit_group;" ::: "memory")
#define CP_WAIT1()  asm volatile("cp.async.wait_group 1;" ::: "memory")
#define CP_WAIT0()  asm volatile("cp.async.wait_group 0;" ::: "memory")

__device__ __forceinline__ void split22(float a, float b, uint32_t& h, uint32_t& l) {
    __half2 hh = __floats2half2_rn(a, b);
    float2 f = __half22float2(hh);
    __half2 ll = __floats2half2_rn(a - f.x, b - f.y);
    h = *(uint32_t*)&hh;
    l = *(uint32_t*)&ll;
}

#define ASTR 40
#define BUFH (128 * ASTR)
#define GEMM_SMEM_BYTES (2 * 4 * BUFH * 2)

// ---------------------------------------------------------------------------
// Conversion kernels
// ---------------------------------------------------------------------------
__global__ __launch_bounds__(256) void conv_split_kernel(
    const float* __restrict__ src, __half* __restrict__ dh,
    __half* __restrict__ dl, int n4)
{
    int i = blockIdx.x * 256 + threadIdx.x;
    if (i >= n4) return;
    float4 v = ((const float4*)src)[i];
    uint32_t h0, l0, h1, l1;
    split22(v.x, v.y, h0, l0);
    split22(v.z, v.w, h1, l1);
    ((uint2*)dh)[i] = make_uint2(h0, h1);
    ((uint2*)dl)[i] = make_uint2(l0, l1);
}

__global__ __launch_bounds__(256) void conv_wT_kernel(
    const float* __restrict__ W, __half* __restrict__ WhT,
    __half* __restrict__ WlT, int N)
{
    __shared__ float ts[32][33];
    int n0 = blockIdx.x * 32, k0 = blockIdx.y * 32;
    int tx = threadIdx.x & 31, ty = threadIdx.x >> 5;
#pragma unroll
    for (int r = 0; r < 32; r += 8)
        ts[ty + r][tx] = W[(size_t)(k0 + ty + r) * N + n0 + tx];
    __syncthreads();
#pragma unroll
    for (int r = 0; r < 32; r += 8) {
        float v = ts[tx][ty + r];
        __half h = __float2half_rn(v);
        __half l = __float2half_rn(v - __half2float(h));
        size_t o = (size_t)(n0 + ty + r) * HIDDEN + k0 + tx;
        WhT[o] = h;
        WlT[o] = l;
    }
}

// ---------------------------------------------------------------------------
// HMMA GEMM mainloop (round-6, proven)
// ---------------------------------------------------------------------------
__device__ __forceinline__ void stage_chunk(
    const __half* __restrict__ Ah, const __half* __restrict__ Al,
    const __half* __restrict__ BhT, const __half* __restrict__ BlT,
    int bm, int bn, int k0, int tid, uint32_t sbuf)
{
    for (int i = tid; i < 512; i += 256) {
        int row = i >> 2, q = i & 3;
        uint32_t doff = (uint32_t)((row * ASTR + q * 8) * 2);
        size_t soA = (size_t)(bm + row) * HIDDEN + k0 + q * 8;
        size_t soB = (size_t)(bn + row) * HIDDEN + k0 + q * 8;
        cpa16(sbuf + doff,                Ah + soA);
        cpa16(sbuf + BUFH * 2 + doff,     Al + soA);
        cpa16(sbuf + 2 * BUFH * 2 + doff, BhT + soB);
        cpa16(sbuf + 3 * BUFH * 2 + doff, BlT + soB);
    }
}

__device__ __forceinline__ void hmma_gemm_main(
    const __half* __restrict__ Ah, const __half* __restrict__ Al,
    const __half* __restrict__ BhT, const __half* __restrict__ BlT,
    int bm, int bn, int tid, uint32_t sbase, float acc[2][8][4])
{
    const int lane = tid & 31, wid = tid >> 5;
    const int m_off = (wid & 3) * 32, n_off = (wid >> 2) * 64;
    const int arow = lane & 15;
    const int acolb = (lane >> 4) << 3;
    const int brow = (lane & 7) + ((lane >> 4) << 3);
    const int bcolb = ((lane >> 3) & 1) << 3;
    const uint32_t bufbytes = 4 * BUFH * 2;

    stage_chunk(Ah, Al, BhT, BlT, bm, bn, 0, tid, sbase);
    CP_COMMIT();

    for (int c = 0; c < 32; c++) {
        uint32_t cur = sbase + (uint32_t)(c & 1) * bufbytes;
        if (c + 1 < 32) {
            stage_chunk(Ah, Al, BhT, BlT, bm, bn, (c + 1) * 32, tid,
                        sbase + (uint32_t)((c + 1) & 1) * bufbytes);
            CP_COMMIT();
            CP_WAIT1();
        } else {
            CP_WAIT0();
        }
        __syncthreads();

        uint32_t uAh = cur, uAl = cur + BUFH * 2;
        uint32_t uBh = cur + 2 * BUFH * 2, uBl = cur + 3 * BUFH * 2;
#pragma unroll
        for (int kk = 0; kk < 32; kk += 16) {
            uint32_t aH[2][4], aL[2][4], bH[8][2], bL[8][2];
#pragma unroll
            for (int t = 0; t < 2; t++) {
                uint32_t off = (uint32_t)(((m_off + t * 16 + arow) * ASTR
                                           + kk + acolb) * 2);
                ldm4(aH[t][0], aH[t][1], aH[t][2], aH[t][3], uAh + off);
                ldm4(aL[t][0], aL[t][1], aL[t][2], aL[t][3], uAl + off);
            }
#pragma unroll
            for (int p = 0; p < 4; p++) {
                uint32_t off = (uint32_t)(((n_off + p * 16 + brow) * ASTR
                                           + kk + bcolb) * 2);
                ldm4(bH[2 * p][0], bH[2 * p][1], bH[2 * p + 1][0], bH[2 * p + 1][1],
                     uBh + off);
                ldm4(bL[2 * p][0], bL[2 * p][1], bL[2 * p + 1][0], bL[2 * p + 1][1],
                     uBl + off);
            }
#pragma unroll
            for (int mt = 0; mt < 2; mt++)
#pragma unroll
                for (int nt = 0; nt < 8; nt++) {
                    mma_f16(acc[mt][nt], aH[mt], bH[nt]);
                    mma_f16(acc[mt][nt], aH[mt], bL[nt]);
                    mma_f16(acc[mt][nt], aL[mt], bH[nt]);
                }
        }
        __syncthreads();
    }
}

// ---------------------------------------------------------------------------
// GEMM 1: qkv -> fp32 q/k/v outputs + fp16 h/l copies (q pre-scaled by 1/8)
// ---------------------------------------------------------------------------
__global__ __launch_bounds__(256, 1) void gemm_qkv_mma(
    const float* __restrict__ bias,
    float* __restrict__ qo, float* __restrict__ ko, float* __restrict__ vo)
{
    extern __shared__ __half dynsm[];
    int tid = threadIdx.x, lane = tid & 31, wid = tid >> 5;
    int bm = blockIdx.y * 128, bn = blockIdx.x * 128;
    float acc[2][8][4] = {};

    hmma_gemm_main(g_xh, g_xl, g_wqkvT_h, g_wqkvT_l, bm, bn, tid,
                   smem_u32(dynsm), acc);

    const int m_off = (wid & 3) * 32, n_off = (wid >> 2) * 64;
    int r = lane >> 2, c2 = (lane & 3) << 1;
#pragma unroll
    for (int mt = 0; mt < 2; mt++) {
        int m0 = bm + m_off + mt * 16 + r;
        int m1 = m0 + 8;
        int bb0 = m0 >> 11, s0 = m0 & (SEQ - 1);
        int bb1 = m1 >> 11, s1 = m1 & (SEQ - 1);
#pragma unroll
        for (int nt = 0; nt < 8; nt++) {
            int n = bn + n_off + nt * 8 + c2;
            float2 bv = *(const float2*)&bias[n];
            int t = n >> 10, hh = (n >> 6) & 15, dc = n & 63;
            float* base = (t == 0) ? qo : ((t == 1) ? ko : vo);
            __half* dh = (t == 0) ? g_qh : ((t == 1) ? g_kh : g_vh);
            __half* dl = (t == 0) ? g_ql : ((t == 1) ? g_kl : g_vl);
            float sc = (t == 0) ? 0.125f : 1.0f;
            float v00 = acc[mt][nt][0] + bv.x, v01 = acc[mt][nt][1] + bv.y;
            float v10 = acc[mt][nt][2] + bv.x, v11 = acc[mt][nt][3] + bv.y;
            size_t off0 = ((size_t)(bb0 * NHEADS + hh) * SEQ + s0) * HDIM + dc;
            size_t off1 = ((size_t)(bb1 * NHEADS + hh) * SEQ + s1) * HDIM + dc;
            *(float2*)&base[off0] = make_float2(v00, v01);
            *(float2*)&base[off1] = make_float2(v10, v11);
            uint32_t h2, l2;
            split22(v00 * sc, v01 * sc, h2, l2);
            *(uint32_t*)&dh[off0] = h2; *(uint32_t*)&dl[off0] = l2;
            split22(v10 * sc, v11 * sc, h2, l2);
            *(uint32_t*)&dh[off1] = h2; *(uint32_t*)&dl[off1] = l2;
        }
    }
}

// ---------------------------------------------------------------------------
// GEMM 2: output = ctx @ W_out + b_out
// ---------------------------------------------------------------------------
__global__ __launch_bounds__(256, 1) void gemm_out_mma(
    const float* __restrict__ bias, float* __restrict__ C)
{
    extern __shared__ __half dynsm[];
    int tid = threadIdx.x, lane = tid & 31, wid = tid >> 5;
    int bm = blockIdx.y * 128, bn = blockIdx.x * 128;
    float acc[2][8][4] = {};

    hmma_gemm_main(g_ctxh, g_ctxl, g_woutT_h, g_woutT_l, bm, bn, tid,
                   smem_u32(dynsm), acc);

    const int m_off = (wid & 3) * 32, n_off = (wid >> 2) * 64;
    int r = lane >> 2, c2 = (lane & 3) << 1;
#pragma unroll
    for (int mt = 0; mt < 2; mt++) {
        int m0 = bm + m_off + mt * 16 + r;
        int m1 = m0 + 8;
#pragma unroll
        for (int nt = 0; nt < 8; nt++) {
            int n = bn + n_off + nt * 8 + c2;
            float2 bv = *(const float2*)&bias[n];
            *(float2*)&C[(size_t)m0 * HIDDEN + n] =
                make_float2(acc[mt][nt][0] + bv.x, acc[mt][nt][1] + bv.y);
            *(float2*)&C[(size_t)m1 * HIDDEN + n] =
                make_float2(acc[mt][nt][2] + bv.x, acc[mt][nt][3] + bv.y);
        }
    }
}

// ---------------------------------------------------------------------------
// Flash attention on HMMA. 128 Q rows/block, 64-key tiles, fp16 h/l 3-term.
// Attention smem row stride AST2=72 halves (64 data + 8 pad).
// ---------------------------------------------------------------------------
#define KT 64
#define QT 128
#define AST2 72
#define QARR (128 * AST2)          // halves per Q array (h or l)
#define KV_OFF (2 * QARR)          // halves offset of kv buffers
#define ARR2 (64 * AST2)           // halves per K/V array
#define KVBUF (4 * ARR2)           // halves per kv double-buffer slot
#define ATTN_SMEM_BYTES ((KV_OFF + 2 * KVBUF) * 2 + 2 * 64 * 4)

__device__ __forceinline__ void stage_kv(
    const __half* Kh, const __half* Kl, const __half* Vh, const __half* Vl,
    int k0, int tid, uint32_t sbuf)
{
    for (int i = tid; i < 512; i += 256) {
        int row = i >> 3, q = i & 7;
        uint32_t doff = (uint32_t)((row * AST2 + q * 8) * 2);
        size_t src = (size_t)(k0 + row) * HDIM + q * 8;
        cpa16(sbuf + doff,                Kh + src);
        cpa16(sbuf + ARR2 * 2 + doff,     Kl + src);
        cpa16(sbuf + 2 * ARR2 * 2 + doff, Vh + src);
        cpa16(sbuf + 3 * ARR2 * 2 + doff, Vl + src);
    }
}

__global__ __launch_bounds__(256, 1) void attn_mma(const int* __restrict__ mask)
{
    extern __shared__ __half asm_[];
    uint32_t sb = smem_u32(asm_);
    float* mbias = (float*)(asm_ + KV_OFF + 2 * KVBUF);
    int tid = threadIdx.x, lane = tid & 31, wid = tid >> 5;
    int qt = gridDim.x - 1 - blockIdx.x;      // long tiles first
    int h = blockIdx.y, b = blockIdx.z;
    int bh = b * NHEADS + h;
    int qbase = qt * QT;
    size_t qoff = ((size_t)bh * SEQ + qbase) * HDIM;
    const __half* Qh = g_qh + qoff;
    const __half* Ql = g_ql + qoff;
    size_t kvoff = (size_t)bh * SEQ * HDIM;
    const __half *Kh = g_kh + kvoff, *Kl = g_kl + kvoff;
    const __half *Vh = g_vh + kvoff, *Vl = g_vl + kvoff;

    // stage Q (group 0): 128 rows x 64 halves
    for (int i = tid; i < 1024; i += 256) {
        int row = i >> 3, q = i & 7;
        uint32_t doff = (uint32_t)((row * AST2 + q * 8) * 2);
        size_t src = (size_t)row * HDIM + q * 8;
        cpa16(sb + doff,            Qh + src);
        cpa16(sb + QARR * 2 + doff, Ql + src);
    }
    CP_COMMIT();

    const int nkt = 2 * qt + 2;
    stage_kv(Kh, Kl, Vh, Vl, 0, tid, sb + KV_OFF * 2);   // group 1
    CP_COMMIT();
    CP_WAIT1();          // Q ready
    __syncthreads();

    // persistent Q fragments
    const int m_off = wid * 16;
    uint32_t qah[4][4], qal[4][4];
    {
        int row = m_off + (lane & 15);
        int colb = 8 * (lane >> 4);
#pragma unroll
        for (int kt2 = 0; kt2 < 4; kt2++) {
            uint32_t a = sb + (uint32_t)((row * AST2 + kt2 * 16 + colb) * 2);
            ldm4(qah[kt2][0], qah[kt2][1], qah[kt2][2], qah[kt2][3], a);
            ldm4(qal[kt2][0], qal[kt2][1], qal[kt2][2], qal[kt2][3],
                 a + QARR * 2);
        }
    }

    float o[8][4] = {};
    float m0 = -1e30f, m1 = -1e30f, l0 = 0.f, l1 = 0.f;
    const int g = lane >> 2, c2 = (lane & 3) << 1;
    const int brow = (lane & 7) + ((lane >> 4) << 3);
    const int bcolb = ((lane >> 3) & 1) << 3;
    const int vrow = lane & 15, vcolb = 8 * (lane >> 4);
    const int row0 = qbase + m_off + g, row1 = row0 + 8;

    for (int c = 0; c < nkt; c++) {
        uint32_t cur = sb + (uint32_t)((KV_OFF + (c & 1) * KVBUF) * 2);
        if (c + 1 < nkt) {
            stage_kv(Kh, Kl, Vh, Vl, (c + 1) * KT, tid,
                     sb + (uint32_t)((KV_OFF + ((c + 1) & 1) * KVBUF) * 2));
            CP_COMMIT();
            CP_WAIT1();
        } else {
            CP_WAIT0();
        }
        if (tid < 64)
            mbias[(c & 1) * 64 + tid] =
                (mask[b * SEQ + c * KT + tid] == 0) ? -1e30f : 0.0f;
        __syncthreads();

        uint32_t uKh = cur, uKl = cur + ARR2 * 2;
        uint32_t uVh = cur + 2 * ARR2 * 2, uVl = cur + 3 * ARR2 * 2;

        // ---- S = Q K^T (3-term) ----
        float s[8][4] = {};
#pragma unroll
        for (int kk2 = 0; kk2 < 4; kk2++) {
            uint32_t kbh[4][4], kbl[4][4];
#pragma unroll
            for (int p = 0; p < 4; p++) {
                uint32_t a = (uint32_t)(((p * 16 + brow) * AST2
                                         + kk2 * 16 + bcolb) * 2);
                ldm4(kbh[p][0], kbh[p][1], kbh[p][2], kbh[p][3], uKh + a);
                ldm4(kbl[p][0], kbl[p][1], kbl[p][2], kbl[p][3], uKl + a);
            }
#pragma unroll
            for (int nt = 0; nt < 8; nt++) {
                int p = nt >> 1, ix = (nt & 1) * 2;
                mma_f16(s[nt], qah[kk2], &kbh[p][ix]);
                mma_f16(s[nt], qah[kk2], &kbl[p][ix]);
                mma_f16(s[nt], qal[kk2], &kbh[p][ix]);
            }
        }

        // ---- mask + causal ----
        int k0 = c * KT;
        bool diag = (k0 + KT - 1 > row0) || (k0 + KT - 1 > row1);
#pragma unroll
        for (int nt = 0; nt < 8; nt++) {
            int colb = k0 + nt * 8 + c2;
            float mb0 = mbias[(c & 1) * 64 + nt * 8 + c2];
            float mb1 = mbias[(c & 1) * 64 + nt * 8 + c2 + 1];
            s[nt][0] += mb0; s[nt][1] += mb1;
            s[nt][2] += mb0; s[nt][3] += mb1;
            if (diag) {
                if (colb     > row0) s[nt][0] = -1e30f;
                if (colb + 1 > row0) s[nt][1] = -1e30f;
                if (colb     > row1) s[nt][2] = -1e30f;
                if (colb + 1 > row1) s[nt][3] = -1e30f;
            }
        }

        // ---- online softmax (rows live on lane quads) ----
        float mx0 = -1e30f, mx1 = -1e30f;
#pragma unroll
        for (int nt = 0; nt < 8; nt++) {
            mx0 = fmaxf(mx0, fmaxf(s[nt][0], s[nt][1]));
            mx1 = fmaxf(mx1, fmaxf(s[nt][2], s[nt][3]));
        }
        mx0 = fmaxf(mx0, __shfl_xor_sync(0xffffffffu, mx0, 1));
        mx0 = fmaxf(mx0, __shfl_xor_sync(0xffffffffu, mx0, 2));
        mx1 = fmaxf(mx1, __shfl_xor_sync(0xffffffffu, mx1, 1));
        mx1 = fmaxf(mx1, __shfl_xor_sync(0xffffffffu, mx1, 2));
        float mn0 = fmaxf(m0, mx0), mn1 = fmaxf(m1, mx1);
        float fac0 = __expf(m0 - mn0), fac1 = __expf(m1 - mn1);
        m0 = mn0; m1 = mn1;
        float rs0 = 0.f, rs1 = 0.f;
#pragma unroll
        for (int nt = 0; nt < 8; nt++) {
            s[nt][0] = __expf(s[nt][0] - mn0); rs0 += s[nt][0];
            s[nt][1] = __expf(s[nt][1] - mn0); rs0 += s[nt][1];
            s[nt][2] = __expf(s[nt][2] - mn1); rs1 += s[nt][2];
            s[nt][3] = __expf(s[nt][3] - mn1); rs1 += s[nt][3];
        }
        rs0 += __shfl_xor_sync(0xffffffffu, rs0, 1);
        rs0 += __shfl_xor_sync(0xffffffffu, rs0, 2);
        rs1 += __shfl_xor_sync(0xffffffffu, rs1, 1);
        rs1 += __shfl_xor_sync(0xffffffffu, rs1, 2);
        l0 = l0 * fac0 + rs0;
        l1 = l1 * fac1 + rs1;
#pragma unroll
        for (int nt = 0; nt < 8; nt++) {
            o[nt][0] *= fac0; o[nt][1] *= fac0;
            o[nt][2] *= fac1; o[nt][3] *= fac1;
        }

        // ---- P fragments (accumulator layout == A-operand layout) ----
        uint32_t pah[4][4], pal[4][4];
#pragma unroll
        for (int kt2 = 0; kt2 < 4; kt2++) {
            split22(s[2 * kt2][0],     s[2 * kt2][1],     pah[kt2][0], pal[kt2][0]);
            split22(s[2 * kt2][2],     s[2 * kt2][3],     pah[kt2][1], pal[kt2][1]);
            split22(s[2 * kt2 + 1][0], s[2 * kt2 + 1][1], pah[kt2][2], pal[kt2][2]);
            split22(s[2 * kt2 + 1][2], s[2 * kt2 + 1][3], pah[kt2][3], pal[kt2][3]);
        }

        // ---- O += P V (3-term; V via ldmatrix.trans) ----
#pragma unroll
        for (int kk2 = 0; kk2 < 4; kk2++) {
            uint32_t vbh[4][4], vbl[4][4];
#pragma unroll
            for (int n0i = 0; n0i < 4; n0i++) {
                uint32_t a = (uint32_t)(((kk2 * 16 + vrow) * AST2
                                         + n0i * 16 + vcolb) * 2);
                ldm4t(vbh[n0i][0], vbh[n0i][1], vbh[n0i][2], vbh[n0i][3], uVh + a);
                ldm4t(vbl[n0i][0], vbl[n0i][1], vbl[n0i][2], vbl[n0i][3], uVl + a);
            }
#pragma unroll
            for (int nt = 0; nt < 8; nt++) {
                int n0i = nt >> 1, ix = (nt & 1) * 2;
                mma_f16(o[nt], pah[kk2], &vbh[n0i][ix]);
                mma_f16(o[nt], pah[kk2], &vbl[n0i][ix]);
                mma_f16(o[nt], pal[kk2], &vbh[n0i][ix]);
            }
        }
        __syncthreads();
    }

    // ---- epilogue: normalize, write ctx h/l ----
    float inv0 = 1.0f / l0, inv1 = 1.0f / l1;
    size_t base0 = ((size_t)(b * SEQ) + row0) * HIDDEN + h * HDIM + c2;
    size_t base1 = base0 + (size_t)8 * HIDDEN;
#pragma unroll
    for (int nt = 0; nt < 8; nt++) {
        uint32_t h2, l2;
        split22(o[nt][0] * inv0, o[nt][1] * inv0, h2, l2);
        *(uint32_t*)&g_ctxh[base0 + nt * 8] = h2;
        *(uint32_t*)&g_ctxl[base0 + nt * 8] = l2;
        split22(o[nt][2] * inv1, o[nt][3] * inv1, h2, l2);
        *(uint32_t*)&g_ctxh[base1 + nt * 8] = h2;
        *(uint32_t*)&g_ctxl[base1 + nt * 8] = l2;
    }
}

// ---------------------------------------------------------------------------
extern "C" void kernel_launch(void* const* d_in, const int* in_sizes, int n_in,
                              void* d_out, int out_size) {
    const float* x    = (const float*)d_in[0];
    const int*   mask = (const int*)d_in[1];
    const float* Wqkv = (const float*)d_in[2];
    const float* bqkv = (const float*)d_in[3];
    const float* Wout = (const float*)d_in[4];
    const float* bout = (const float*)d_in[5];

    float* out = (float*)d_out;                     // [B,S,H]
    float* qo = out + (size_t)MTOT * HIDDEN;        // [B,h,S,d]
    float* ko = qo + (size_t)MTOT * HIDDEN;
    float* vo = ko + (size_t)MTOT * HIDDEN;

    cudaFuncSetAttribute(gemm_qkv_mma,
                         cudaFuncAttributeMaxDynamicSharedMemorySize, GEMM_SMEM_BYTES);
    cudaFuncSetAttribute(gemm_out_mma,
                         cudaFuncAttributeMaxDynamicSharedMemorySize, GEMM_SMEM_BYTES);
    cudaFuncSetAttribute(attn_mma,
                         cudaFuncAttributeMaxDynamicSharedMemorySize, ATTN_SMEM_BYTES);

    __half *xh, *xl, *wqh, *wql, *woh, *wol;
    cudaGetSymbolAddress((void**)&xh, g_xh);
    cudaGetSymbolAddress((void**)&xl, g_xl);
    cudaGetSymbolAddress((void**)&wqh, g_wqkvT_h);
    cudaGetSymbolAddress((void**)&wql, g_wqkvT_l);
    cudaGetSymbolAddress((void**)&woh, g_woutT_h);
    cudaGetSymbolAddress((void**)&wol, g_woutT_l);

    conv_split_kernel<<<(MTOT * HIDDEN / 4 + 255) / 256, 256>>>(
        x, xh, xl, MTOT * HIDDEN / 4);
    conv_wT_kernel<<<dim3(3 * HIDDEN / 32, HIDDEN / 32), 256>>>(
        Wqkv, wqh, wql, 3 * HIDDEN);
    conv_wT_kernel<<<dim3(HIDDEN / 32, HIDDEN / 32), 256>>>(
        Wout, woh, wol, HIDDEN);

    gemm_qkv_mma<<<dim3(24, 32), 256, GEMM_SMEM_BYTES>>>(bqkv, qo, ko, vo);
    attn_mma<<<dim3(SEQ / QT, NHEADS, BATCH), 256, ATTN_SMEM_BYTES>>>(mask);
    gemm_out_mma<<<dim3(8, 32), 256, GEMM_SMEM_BYTES>>>(bout, out);
}

// round 10
// speedup vs baseline: 2.3718x; 1.0373x over previous
#include <cuda_runtime.h>
#include <cuda_fp16.h>
#include <cstdint>

#define HIDDEN 1024
#define NHEADS 16
#define HDIM 64
#define BATCH 2
#define SEQ 2048
#define MTOT (BATCH*SEQ)

typedef unsigned long long ull;

// ---- fp16 h/l scratch ------------------------------------------------------
__device__ __half g_xh[(size_t)MTOT * HIDDEN];
__device__ __half g_xl[(size_t)MTOT * HIDDEN];
__device__ __half g_wqkvT_h[(size_t)3 * HIDDEN * HIDDEN];
__device__ __half g_wqkvT_l[(size_t)3 * HIDDEN * HIDDEN];
__device__ __half g_woutT_h[(size_t)HIDDEN * HIDDEN];
__device__ __half g_woutT_l[(size_t)HIDDEN * HIDDEN];
__device__ __half g_ctxh[(size_t)MTOT * HIDDEN];
__device__ __half g_ctxl[(size_t)MTOT * HIDDEN];
// attention operands, [B,h,S,d]; q pre-scaled by 0.125
__device__ __half g_qh[(size_t)MTOT * HIDDEN];
__device__ __half g_ql[(size_t)MTOT * HIDDEN];
__device__ __half g_kh[(size_t)MTOT * HIDDEN];
__device__ __half g_kl[(size_t)MTOT * HIDDEN];
__device__ __half g_vh[(size_t)MTOT * HIDDEN];
__device__ __half g_vl[(size_t)MTOT * HIDDEN];

// ======================= helpers ============================================
__device__ __forceinline__ uint32_t smem_u32(const void* p) {
    uint32_t a;
    asm("{ .reg .u64 t; cvta.to.shared.u64 t, %1; cvt.u32.u64 %0, t; }"
        : "=r"(a) : "l"(p));
    return a;
}
__device__ __forceinline__ void ldm4(uint32_t& r0, uint32_t& r1,
                                     uint32_t& r2, uint32_t& r3, uint32_t a) {
    asm volatile("ldmatrix.sync.aligned.m8n8.x4.shared.b16 {%0,%1,%2,%3}, [%4];"
                 : "=r"(r0), "=r"(r1), "=r"(r2), "=r"(r3) : "r"(a));
}
__device__ __forceinline__ void ldm4t(uint32_t& r0, uint32_t& r1,
                                      uint32_t& r2, uint32_t& r3, uint32_t a) {
    asm volatile("ldmatrix.sync.aligned.m8n8.x4.trans.shared.b16 {%0,%1,%2,%3}, [%4];"
                 : "=r"(r0), "=r"(r1), "=r"(r2), "=r"(r3) : "r"(a));
}
__device__ __forceinline__ void mma_f16(float d[4], const uint32_t a[4],
                                        const uint32_t b[2]) {
    asm volatile(
        "mma.sync.aligned.m16n8k16.row.col.f32.f16.f16.f32 "
        "{%0,%1,%2,%3}, {%4,%5,%6,%7}, {%8,%9}, {%0,%1,%2,%3};"
        : "+f"(d[0]), "+f"(d[1]), "+f"(d[2]), "+f"(d[3])
        : "r"(a[0]), "r"(a[1]), "r"(a[2]), "r"(a[3]), "r"(b[0]), "r"(b[1]));
}
__device__ __forceinline__ void cpa16(uint32_t dst, const void* src) {
    asm volatile("cp.async.cg.shared.global [%0], [%1], 16;"
                 :: "r"(dst), "l"(src) : "memory");
}
#define CP_COMMIT() asm volatile("cp.async.commit_group;" ::: "memory")
#define CP_WAIT2()  asm volatile("cp.async.wait_group 2;" ::: "memory")
#define CP_WAIT1()  asm volatile("cp.async.wait_group 1;" ::: "memory")
#define CP_WAIT0()  asm volatile("cp.async.wait_group 0;" ::: "memory")

__device__ __forceinline__ void split22(float a, float b, uint32_t& h, uint32_t& l) {
    __half2 hh = __floats2half2_rn(a, b);
    float2 f = __half22float2(hh);
    __half2 ll = __floats2half2_rn(a - f.x, b - f.y);
    h = *(uint32_t*)&hh;
    l = *(uint32_t*)&ll;
}

#define ASTR 40
#define BUFH (128 * ASTR)
#define NSTAGE 3
#define GEMM_SMEM_BYTES (NSTAGE * 4 * BUFH * 2)

// ---------------------------------------------------------------------------
// Conversion kernels
// ---------------------------------------------------------------------------
__global__ __launch_bounds__(256) void conv_split_kernel(
    const float* __restrict__ src, __half* __restrict__ dh,
    __half* __restrict__ dl, int n4)
{
    int i = blockIdx.x * 256 + threadIdx.x;
    if (i >= n4) return;
    float4 v = ((const float4*)src)[i];
    uint32_t h0, l0, h1, l1;
    split22(v.x, v.y, h0, l0);
    split22(v.z, v.w, h1, l1);
    ((uint2*)dh)[i] = make_uint2(h0, h1);
    ((uint2*)dl)[i] = make_uint2(l0, l1);
}

__global__ __launch_bounds__(256) void conv_wT_kernel(
    const float* __restrict__ W, __half* __restrict__ WhT,
    __half* __restrict__ WlT, int N)
{
    __shared__ float ts[32][33];
    int n0 = blockIdx.x * 32, k0 = blockIdx.y * 32;
    int tx = threadIdx.x & 31, ty = threadIdx.x >> 5;
#pragma unroll
    for (int r = 0; r < 32; r += 8)
        ts[ty + r][tx] = W[(size_t)(k0 + ty + r) * N + n0 + tx];
    __syncthreads();
#pragma unroll
    for (int r = 0; r < 32; r += 8) {
        float v = ts[tx][ty + r];
        __half h = __float2half_rn(v);
        __half l = __float2half_rn(v - __half2float(h));
        size_t o = (size_t)(n0 + ty + r) * HIDDEN + k0 + tx;
        WhT[o] = h;
        WlT[o] = l;
    }
}

// q/k/v fp32 [B,h,S,d] -> fp16 h/l copies (q scaled by 1/8). 3*MTOT*HIDDEN/4 thr
__global__ __launch_bounds__(256) void conv_attn_split(
    const float* __restrict__ q, const float* __restrict__ k,
    const float* __restrict__ v)
{
    const int n4 = MTOT * HIDDEN / 4;
    int i = blockIdx.x * 256 + threadIdx.x;
    int region = i / n4;
    int j = i - region * n4;
    const float* src = (region == 0) ? q : ((region == 1) ? k : v);
    __half* dh = (region == 0) ? g_qh : ((region == 1) ? g_kh : g_vh);
    __half* dl = (region == 0) ? g_ql : ((region == 1) ? g_kl : g_vl);
    float sc = (region == 0) ? 0.125f : 1.0f;
    float4 val = ((const float4*)src)[j];
    uint32_t h0, l0, h1, l1;
    split22(val.x * sc, val.y * sc, h0, l0);
    split22(val.z * sc, val.w * sc, h1, l1);
    ((uint2*)dh)[j] = make_uint2(h0, h1);
    ((uint2*)dl)[j] = make_uint2(l0, l1);
}

// ---------------------------------------------------------------------------
// HMMA GEMM mainloop: 3-stage cp.async pipeline, one barrier per chunk.
// ---------------------------------------------------------------------------
__device__ __forceinline__ void stage_chunk(
    const __half* __restrict__ Ah, const __half* __restrict__ Al,
    const __half* __restrict__ BhT, const __half* __restrict__ BlT,
    int bm, int bn, int k0, int tid, uint32_t sbuf)
{
    for (int i = tid; i < 512; i += 256) {
        int row = i >> 2, q = i & 3;
        uint32_t doff = (uint32_t)((row * ASTR + q * 8) * 2);
        size_t soA = (size_t)(bm + row) * HIDDEN + k0 + q * 8;
        size_t soB = (size_t)(bn + row) * HIDDEN + k0 + q * 8;
        cpa16(sbuf + doff,                Ah + soA);
        cpa16(sbuf + BUFH * 2 + doff,     Al + soA);
        cpa16(sbuf + 2 * BUFH * 2 + doff, BhT + soB);
        cpa16(sbuf + 3 * BUFH * 2 + doff, BlT + soB);
    }
}

__device__ __forceinline__ void hmma_gemm_main(
    const __half* __restrict__ Ah, const __half* __restrict__ Al,
    const __half* __restrict__ BhT, const __half* __restrict__ BlT,
    int bm, int bn, int tid, uint32_t sbase, float acc[2][8][4])
{
    const int lane = tid & 31, wid = tid >> 5;
    const int m_off = (wid & 3) * 32, n_off = (wid >> 2) * 64;
    const int arow = lane & 15;
    const int acolb = (lane >> 4) << 3;
    const int brow = (lane & 7) + ((lane >> 4) << 3);
    const int bcolb = ((lane >> 3) & 1) << 3;
    const uint32_t bufbytes = 4 * BUFH * 2;

    stage_chunk(Ah, Al, BhT, BlT, bm, bn, 0, tid, sbase);
    CP_COMMIT();
    stage_chunk(Ah, Al, BhT, BlT, bm, bn, 32, tid, sbase + bufbytes);
    CP_COMMIT();

    for (int c = 0; c < 32; c++) {
        uint32_t cur = sbase + (uint32_t)(c % 3) * bufbytes;
        if (c + 1 < 32) { CP_WAIT1(); } else { CP_WAIT0(); }
        __syncthreads();
        if (c + 2 < 32) {
            stage_chunk(Ah, Al, BhT, BlT, bm, bn, (c + 2) * 32, tid,
                        sbase + (uint32_t)((c + 2) % 3) * bufbytes);
            CP_COMMIT();
        }

        uint32_t uAh = cur, uAl = cur + BUFH * 2;
        uint32_t uBh = cur + 2 * BUFH * 2, uBl = cur + 3 * BUFH * 2;
#pragma unroll
        for (int kk = 0; kk < 32; kk += 16) {
            uint32_t aH[2][4], aL[2][4], bH[8][2], bL[8][2];
#pragma unroll
            for (int t = 0; t < 2; t++) {
                uint32_t off = (uint32_t)(((m_off + t * 16 + arow) * ASTR
                                           + kk + acolb) * 2);
                ldm4(aH[t][0], aH[t][1], aH[t][2], aH[t][3], uAh + off);
                ldm4(aL[t][0], aL[t][1], aL[t][2], aL[t][3], uAl + off);
            }
#pragma unroll
            for (int p = 0; p < 4; p++) {
                uint32_t off = (uint32_t)(((n_off + p * 16 + brow) * ASTR
                                           + kk + bcolb) * 2);
                ldm4(bH[2 * p][0], bH[2 * p][1], bH[2 * p + 1][0], bH[2 * p + 1][1],
                     uBh + off);
                ldm4(bL[2 * p][0], bL[2 * p][1], bL[2 * p + 1][0], bL[2 * p + 1][1],
                     uBl + off);
            }
#pragma unroll
            for (int mt = 0; mt < 2; mt++)
#pragma unroll
                for (int nt = 0; nt < 8; nt++) {
                    mma_f16(acc[mt][nt], aH[mt], bH[nt]);
                    mma_f16(acc[mt][nt], aH[mt], bL[nt]);
                    mma_f16(acc[mt][nt], aL[mt], bH[nt]);
                }
        }
    }
}

// ---------------------------------------------------------------------------
// GEMM 1: qkv -> fp32 q/k/v outputs (h/l copies made by conv_attn_split)
// ---------------------------------------------------------------------------
__global__ __launch_bounds__(256, 1) void gemm_qkv_mma(
    const float* __restrict__ bias,
    float* __restrict__ qo, float* __restrict__ ko, float* __restrict__ vo)
{
    extern __shared__ __half dynsm[];
    int tid = threadIdx.x, lane = tid & 31, wid = tid >> 5;
    int bm = blockIdx.y * 128, bn = blockIdx.x * 128;
    float acc[2][8][4] = {};

    hmma_gemm_main(g_xh, g_xl, g_wqkvT_h, g_wqkvT_l, bm, bn, tid,
                   smem_u32(dynsm), acc);

    const int m_off = (wid & 3) * 32, n_off = (wid >> 2) * 64;
    int r = lane >> 2, c2 = (lane & 3) << 1;
#pragma unroll
    for (int mt = 0; mt < 2; mt++) {
        int m0 = bm + m_off + mt * 16 + r;
        int m1 = m0 + 8;
        int bb0 = m0 >> 11, s0 = m0 & (SEQ - 1);
        int bb1 = m1 >> 11, s1 = m1 & (SEQ - 1);
#pragma unroll
        for (int nt = 0; nt < 8; nt++) {
            int n = bn + n_off + nt * 8 + c2;
            float2 bv = *(const float2*)&bias[n];
            int t = n >> 10, hh = (n >> 6) & 15, dc = n & 63;
            float* base = (t == 0) ? qo : ((t == 1) ? ko : vo);
            size_t off0 = ((size_t)(bb0 * NHEADS + hh) * SEQ + s0) * HDIM + dc;
            size_t off1 = ((size_t)(bb1 * NHEADS + hh) * SEQ + s1) * HDIM + dc;
            *(float2*)&base[off0] =
                make_float2(acc[mt][nt][0] + bv.x, acc[mt][nt][1] + bv.y);
            *(float2*)&base[off1] =
                make_float2(acc[mt][nt][2] + bv.x, acc[mt][nt][3] + bv.y);
        }
    }
}

// ---------------------------------------------------------------------------
// GEMM 2: output = ctx @ W_out + b_out
// ---------------------------------------------------------------------------
__global__ __launch_bounds__(256, 1) void gemm_out_mma(
    const float* __restrict__ bias, float* __restrict__ C)
{
    extern __shared__ __half dynsm[];
    int tid = threadIdx.x, lane = tid & 31, wid = tid >> 5;
    int bm = blockIdx.y * 128, bn = blockIdx.x * 128;
    float acc[2][8][4] = {};

    hmma_gemm_main(g_ctxh, g_ctxl, g_woutT_h, g_woutT_l, bm, bn, tid,
                   smem_u32(dynsm), acc);

    const int m_off = (wid & 3) * 32, n_off = (wid >> 2) * 64;
    int r = lane >> 2, c2 = (lane & 3) << 1;
#pragma unroll
    for (int mt = 0; mt < 2; mt++) {
        int m0 = bm + m_off + mt * 16 + r;
        int m1 = m0 + 8;
#pragma unroll
        for (int nt = 0; nt < 8; nt++) {
            int n = bn + n_off + nt * 8 + c2;
            float2 bv = *(const float2*)&bias[n];
            *(float2*)&C[(size_t)m0 * HIDDEN + n] =
                make_float2(acc[mt][nt][0] + bv.x, acc[mt][nt][1] + bv.y);
            *(float2*)&C[(size_t)m1 * HIDDEN + n] =
                make_float2(acc[mt][nt][2] + bv.x, acc[mt][nt][3] + bv.y);
        }
    }
}

// ---------------------------------------------------------------------------
// Flash attention on HMMA, 3-stage KV pipeline, one barrier per chunk.
// ---------------------------------------------------------------------------
#define KT 64
#define QT 128
#define AST2 72
#define QARR (128 * AST2)
#define KV_OFF (2 * QARR)
#define ARR2 (64 * AST2)
#define KVBUF (4 * ARR2)
#define NKV 3
#define ATTN_SMEM_BYTES ((KV_OFF + NKV * KVBUF) * 2 + 2 * 64 * 4)

__device__ __forceinline__ void stage_kv(
    const __half* Kh, const __half* Kl, const __half* Vh, const __half* Vl,
    int k0, int tid, uint32_t sbuf)
{
    for (int i = tid; i < 512; i += 256) {
        int row = i >> 3, q = i & 7;
        uint32_t doff = (uint32_t)((row * AST2 + q * 8) * 2);
        size_t src = (size_t)(k0 + row) * HDIM + q * 8;
        cpa16(sbuf + doff,                Kh + src);
        cpa16(sbuf + ARR2 * 2 + doff,     Kl + src);
        cpa16(sbuf + 2 * ARR2 * 2 + doff, Vh + src);
        cpa16(sbuf + 3 * ARR2 * 2 + doff, Vl + src);
    }
}

__global__ __launch_bounds__(256, 1) void attn_mma(const int* __restrict__ mask)
{
    extern __shared__ __half asm_[];
    uint32_t sb = smem_u32(asm_);
    float* mbias = (float*)(asm_ + KV_OFF + NKV * KVBUF);
    int tid = threadIdx.x, lane = tid & 31, wid = tid >> 5;
    int qt = gridDim.x - 1 - blockIdx.x;      // long tiles first
    int h = blockIdx.y, b = blockIdx.z;
    int bh = b * NHEADS + h;
    int qbase = qt * QT;
    size_t qoff = ((size_t)bh * SEQ + qbase) * HDIM;
    const __half* Qh = g_qh + qoff;
    const __half* Ql = g_ql + qoff;
    size_t kvoff = (size_t)bh * SEQ * HDIM;
    const __half *Kh = g_kh + kvoff, *Kl = g_kl + kvoff;
    const __half *Vh = g_vh + kvoff, *Vl = g_vl + kvoff;

    // stage Q (group 0): 128 rows x 64 halves
    for (int i = tid; i < 1024; i += 256) {
        int row = i >> 3, q = i & 7;
        uint32_t doff = (uint32_t)((row * AST2 + q * 8) * 2);
        size_t src = (size_t)row * HDIM + q * 8;
        cpa16(sb + doff,            Qh + src);
        cpa16(sb + QARR * 2 + doff, Ql + src);
    }
    CP_COMMIT();

    const int nkt = 2 * qt + 2;   // always >= 2
    stage_kv(Kh, Kl, Vh, Vl, 0, tid, sb + KV_OFF * 2);
    CP_COMMIT();
    stage_kv(Kh, Kl, Vh, Vl, KT, tid, sb + (KV_OFF + KVBUF) * 2);
    CP_COMMIT();
    CP_WAIT2();          // Q ready (kv0, kv1 may still be in flight)
    __syncthreads();

    // persistent Q fragments
    const int m_off = wid * 16;
    uint32_t qah[4][4], qal[4][4];
    {
        int row = m_off + (lane & 15);
        int colb = 8 * (lane >> 4);
#pragma unroll
        for (int kt2 = 0; kt2 < 4; kt2++) {
            uint32_t a = sb + (uint32_t)((row * AST2 + kt2 * 16 + colb) * 2);
            ldm4(qah[kt2][0], qah[kt2][1], qah[kt2][2], qah[kt2][3], a);
            ldm4(qal[kt2][0], qal[kt2][1], qal[kt2][2], qal[kt2][3],
                 a + QARR * 2);
        }
    }

    float o[8][4] = {};
    float m0 = -1e30f, m1 = -1e30f, l0 = 0.f, l1 = 0.f;
    const int g = lane >> 2, c2 = (lane & 3) << 1;
    const int brow = (lane & 7) + ((lane >> 4) << 3);
    const int bcolb = ((lane >> 3) & 1) << 3;
    const int vrow = lane & 15, vcolb = 8 * (lane >> 4);
    const int row0 = qbase + m_off + g, row1 = row0 + 8;

    for (int c = 0; c < nkt; c++) {
        uint32_t cur = sb + (uint32_t)((KV_OFF + (c % 3) * KVBUF) * 2);
        if (c + 1 < nkt) { CP_WAIT1(); } else { CP_WAIT0(); }
        if (tid < 64)
            mbias[(c & 1) * 64 + tid] =
                (mask[b * SEQ + c * KT + tid] == 0) ? -1e30f : 0.0f;
        __syncthreads();
        if (c + 2 < nkt) {
            stage_kv(Kh, Kl, Vh, Vl, (c + 2) * KT, tid,
                     sb + (uint32_t)((KV_OFF + ((c + 2) % 3) * KVBUF) * 2));
            CP_COMMIT();
        }

        uint32_t uKh = cur, uKl = cur + ARR2 * 2;
        uint32_t uVh = cur + 2 * ARR2 * 2, uVl = cur + 3 * ARR2 * 2;

        // ---- S = Q K^T (3-term) ----
        float s[8][4] = {};
#pragma unroll
        for (int kk2 = 0; kk2 < 4; kk2++) {
            uint32_t kbh[4][4], kbl[4][4];
#pragma unroll
            for (int p = 0; p < 4; p++) {
                uint32_t a = (uint32_t)(((p * 16 + brow) * AST2
                                         + kk2 * 16 + bcolb) * 2);
                ldm4(kbh[p][0], kbh[p][1], kbh[p][2], kbh[p][3], uKh + a);
                ldm4(kbl[p][0], kbl[p][1], kbl[p][2], kbl[p][3], uKl + a);
            }
#pragma unroll
            for (int nt = 0; nt < 8; nt++) {
                int p = nt >> 1, ix = (nt & 1) * 2;
                mma_f16(s[nt], qah[kk2], &kbh[p][ix]);
                mma_f16(s[nt], qah[kk2], &kbl[p][ix]);
                mma_f16(s[nt], qal[kk2], &kbh[p][ix]);
            }
        }

        // ---- mask + causal ----
        int k0 = c * KT;
        bool diag = (k0 + KT - 1 > row0) || (k0 + KT - 1 > row1);
#pragma unroll
        for (int nt = 0; nt < 8; nt++) {
            int colb = k0 + nt * 8 + c2;
            float mb0 = mbias[(c & 1) * 64 + nt * 8 + c2];
            float mb1 = mbias[(c & 1) * 64 + nt * 8 + c2 + 1];
            s[nt][0] += mb0; s[nt][1] += mb1;
            s[nt][2] += mb0; s[nt][3] += mb1;
            if (diag) {
                if (colb     > row0) s[nt][0] = -1e30f;
                if (colb + 1 > row0) s[nt][1] = -1e30f;
                if (colb     > row1) s[nt][2] = -1e30f;
                if (colb + 1 > row1) s[nt][3] = -1e30f;
            }
        }

        // ---- online softmax ----
        float mx0 = -1e30f, mx1 = -1e30f;
#pragma unroll
        for (int nt = 0; nt < 8; nt++) {
            mx0 = fmaxf(mx0, fmaxf(s[nt][0], s[nt][1]));
            mx1 = fmaxf(mx1, fmaxf(s[nt][2], s[nt][3]));
        }
        mx0 = fmaxf(mx0, __shfl_xor_sync(0xffffffffu, mx0, 1));
        mx0 = fmaxf(mx0, __shfl_xor_sync(0xffffffffu, mx0, 2));
        mx1 = fmaxf(mx1, __shfl_xor_sync(0xffffffffu, mx1, 1));
        mx1 = fmaxf(mx1, __shfl_xor_sync(0xffffffffu, mx1, 2));
        float mn0 = fmaxf(m0, mx0), mn1 = fmaxf(m1, mx1);
        float fac0 = __expf(m0 - mn0), fac1 = __expf(m1 - mn1);
        m0 = mn0; m1 = mn1;
        float rs0 = 0.f, rs1 = 0.f;
#pragma unroll
        for (int nt = 0; nt < 8; nt++) {
            s[nt][0] = __expf(s[nt][0] - mn0); rs0 += s[nt][0];
            s[nt][1] = __expf(s[nt][1] - mn0); rs0 += s[nt][1];
            s[nt][2] = __expf(s[nt][2] - mn1); rs1 += s[nt][2];
            s[nt][3] = __expf(s[nt][3] - mn1); rs1 += s[nt][3];
        }
        rs0 += __shfl_xor_sync(0xffffffffu, rs0, 1);
        rs0 += __shfl_xor_sync(0xffffffffu, rs0, 2);
        rs1 += __shfl_xor_sync(0xffffffffu, rs1, 1);
        rs1 += __shfl_xor_sync(0xffffffffu, rs1, 2);
        l0 = l0 * fac0 + rs0;
        l1 = l1 * fac1 + rs1;
#pragma unroll
        for (int nt = 0; nt < 8; nt++) {
            o[nt][0] *= fac0; o[nt][1] *= fac0;
            o[nt][2] *= fac1; o[nt][3] *= fac1;
        }

        // ---- P fragments ----
        uint32_t pah[4][4], pal[4][4];
#pragma unroll
        for (int kt2 = 0; kt2 < 4; kt2++) {
            split22(s[2 * kt2][0],     s[2 * kt2][1],     pah[kt2][0], pal[kt2][0]);
            split22(s[2 * kt2][2],     s[2 * kt2][3],     pah[kt2][1], pal[kt2][1]);
            split22(s[2 * kt2 + 1][0], s[2 * kt2 + 1][1], pah[kt2][2], pal[kt2][2]);
            split22(s[2 * kt2 + 1][2], s[2 * kt2 + 1][3], pah[kt2][3], pal[kt2][3]);
        }

        // ---- O += P V ----
#pragma unroll
        for (int kk2 = 0; kk2 < 4; kk2++) {
            uint32_t vbh[4][4], vbl[4][4];
#pragma unroll
            for (int n0i = 0; n0i < 4; n0i++) {
                uint32_t a = (uint32_t)(((kk2 * 16 + vrow) * AST2
                                         + n0i * 16 + vcolb) * 2);
                ldm4t(vbh[n0i][0], vbh[n0i][1], vbh[n0i][2], vbh[n0i][3], uVh + a);
                ldm4t(vbl[n0i][0], vbl[n0i][1], vbl[n0i][2], vbl[n0i][3], uVl + a);
            }
#pragma unroll
            for (int nt = 0; nt < 8; nt++) {
                int n0i = nt >> 1, ix = (nt & 1) * 2;
                mma_f16(o[nt], pah[kk2], &vbh[n0i][ix]);
                mma_f16(o[nt], pah[kk2], &vbl[n0i][ix]);
                mma_f16(o[nt], pal[kk2], &vbh[n0i][ix]);
            }
        }
    }

    // ---- epilogue: normalize, write ctx h/l ----
    float inv0 = 1.0f / l0, inv1 = 1.0f / l1;
    size_t base0 = ((size_t)(b * SEQ) + row0) * HIDDEN + h * HDIM + c2;
    size_t base1 = base0 + (size_t)8 * HIDDEN;
#pragma unroll
    for (int nt = 0; nt < 8; nt++) {
        uint32_t h2, l2;
        split22(o[nt][0] * inv0, o[nt][1] * inv0, h2, l2);
        *(uint32_t*)&g_ctxh[base0 + nt * 8] = h2;
        *(uint32_t*)&g_ctxl[base0 + nt * 8] = l2;
        split22(o[nt][2] * inv1, o[nt][3] * inv1, h2, l2);
        *(uint32_t*)&g_ctxh[base1 + nt * 8] = h2;
        *(uint32_t*)&g_ctxl[base1 + nt * 8] = l2;
    }
}

// ---------------------------------------------------------------------------
extern "C" void kernel_launch(void* const* d_in, const int* in_sizes, int n_in,
                              void* d_out, int out_size) {
    const float* x    = (const float*)d_in[0];
    const int*   mask = (const int*)d_in[1];
    const float* Wqkv = (const float*)d_in[2];
    const float* bqkv = (const float*)d_in[3];
    const float* Wout = (const float*)d_in[4];
    const float* bout = (const float*)d_in[5];

    float* out = (float*)d_out;                     // [B,S,H]
    float* qo = out + (size_t)MTOT * HIDDEN;        // [B,h,S,d]
    float* ko = qo + (size_t)MTOT * HIDDEN;
    float* vo = ko + (size_t)MTOT * HIDDEN;

    cudaFuncSetAttribute(gemm_qkv_mma,
                         cudaFuncAttributeMaxDynamicSharedMemorySize, GEMM_SMEM_BYTES);
    cudaFuncSetAttribute(gemm_out_mma,
                         cudaFuncAttributeMaxDynamicSharedMemorySize, GEMM_SMEM_BYTES);
    cudaFuncSetAttribute(attn_mma,
                         cudaFuncAttributeMaxDynamicSharedMemorySize, ATTN_SMEM_BYTES);

    __half *xh, *xl, *wqh, *wql, *woh, *wol;
    cudaGetSymbolAddress((void**)&xh, g_xh);
    cudaGetSymbolAddress((void**)&xl, g_xl);
    cudaGetSymbolAddress((void**)&wqh, g_wqkvT_h);
    cudaGetSymbolAddress((void**)&wql, g_wqkvT_l);
    cudaGetSymbolAddress((void**)&woh, g_woutT_h);
    cudaGetSymbolAddress((void**)&wol, g_woutT_l);

    conv_split_kernel<<<(MTOT * HIDDEN / 4 + 255) / 256, 256>>>(
        x, xh, xl, MTOT * HIDDEN / 4);
    conv_wT_kernel<<<dim3(3 * HIDDEN / 32, HIDDEN / 32), 256>>>(
        Wqkv, wqh, wql, 3 * HIDDEN);
    conv_wT_kernel<<<dim3(HIDDEN / 32, HIDDEN / 32), 256>>>(
        Wout, woh, wol, HIDDEN);

    gemm_qkv_mma<<<dim3(24, 32), 256, GEMM_SMEM_BYTES>>>(bqkv, qo, ko, vo);
    conv_attn_split<<<3 * MTOT * HIDDEN / 4 / 256, 256>>>(qo, ko, vo);
    attn_mma<<<dim3(SEQ / QT, NHEADS, BATCH), 256, ATTN_SMEM_BYTES>>>(mask);
    gemm_out_mma<<<dim3(8, 32), 256, GEMM_SMEM_BYTES>>>(bout, out);
}